// round 6
// baseline (speedup 1.0000x reference)
#include <cuda_runtime.h>
#include <cuda_bf16.h>

#define T_STEPS 1000
#define BETA_1 1e-4
#define BETA_T 0.02

// ---- compile-time table: (sqrt(alpha_bar[t]), sqrt(1-alpha_bar[t])) ----

struct ScaleTable {
    float2 v[T_STEPS];
};

constexpr double csqrt(double x) {
    double g = x > 1.0 ? x : 1.0;
    for (int i = 0; i < 60; ++i) g = 0.5 * (g + x / g);
    return g;
}

constexpr ScaleTable make_table() {
    ScaleTable tbl{};
    const double slope = (BETA_T - BETA_1) / (double)(T_STEPS - 1);
    double ab = 1.0;
    for (int i = 0; i < T_STEPS; ++i) {
        double beta = BETA_1 + slope * (double)i;
        ab *= (1.0 - beta);
        tbl.v[i].x = (float)csqrt(ab);
        tbl.v[i].y = (float)csqrt(1.0 - ab);
    }
    return tbl;
}

__constant__ ScaleTable g_scales = make_table();

// ---- mix kernel: 2 float4 per thread (offset-split), MLP=4, streaming ----
// Best measured config (R3): regs=32, occ ~85%, DRAM ~86.4%.
// total4 = B * 196. Thread handles i0 and i0 + half.

__global__ void __launch_bounds__(256) ddpm_mix_kernel(
    const float4* __restrict__ images,
    const float4* __restrict__ e,
    const int* __restrict__ t,
    float4* __restrict__ out,
    int half, int total4)
{
    const int i0 = blockIdx.x * 256 + threadIdx.x;
    if (i0 >= half) return;
    const int i1 = i0 + half;
    const bool has1 = (i1 < total4);   // uniformly true for this shape

    // Front-batch all global loads (4 LDG.128 in flight)
    float4 im0 = __ldcs(&images[i0]);
    float4 ee0 = __ldcs(&e[i0]);
    float4 im1, ee1;
    if (has1) {
        im1 = __ldcs(&images[i1]);
        ee1 = __ldcs(&e[i1]);
    }

    const unsigned b0 = (unsigned)i0 / 196u;
    const float2 sc0 = g_scales.v[__ldg(&t[b0])];

    float4 o0;
    o0.x = fmaf(sc0.x, im0.x, sc0.y * ee0.x);
    o0.y = fmaf(sc0.x, im0.y, sc0.y * ee0.y);
    o0.z = fmaf(sc0.x, im0.z, sc0.y * ee0.z);
    o0.w = fmaf(sc0.x, im0.w, sc0.y * ee0.w);
    __stcs(&out[i0], o0);

    if (has1) {
        const unsigned b1 = (unsigned)i1 / 196u;
        const float2 sc1 = g_scales.v[__ldg(&t[b1])];
        float4 o1;
        o1.x = fmaf(sc1.x, im1.x, sc1.y * ee1.x);
        o1.y = fmaf(sc1.x, im1.y, sc1.y * ee1.y);
        o1.z = fmaf(sc1.x, im1.z, sc1.y * ee1.z);
        o1.w = fmaf(sc1.x, im1.w, sc1.y * ee1.w);
        __stcs(&out[i1], o1);
    }
}

extern "C" void kernel_launch(void* const* d_in, const int* in_sizes, int n_in,
                              void* d_out, int out_size) {
    const float4* images = (const float4*)d_in[0];
    const float4* e      = (const float4*)d_in[1];
    const int*    t      = (const int*)d_in[2];
    float4* out          = (float4*)d_out;

    const int B = in_sizes[2];
    const int total4 = B * 196;
    const int half = (total4 + 1) / 2;
    const int grid = (half + 255) / 256;

    ddpm_mix_kernel<<<grid, 256>>>(images, e, t, out, half, total4);
}

// round 7
// speedup vs baseline: 1.0078x; 1.0078x over previous
#include <cuda_runtime.h>
#include <cuda_bf16.h>

#define T_STEPS 1000
#define BETA_1 1e-4
#define BETA_T 0.02

// ---- compile-time table: (sqrt(alpha_bar[t]), sqrt(1-alpha_bar[t])) ----
// Depends only on compile-time constants; baked into __constant__ memory so
// the graph has a single kernel node and zero table-init cost at runtime.

struct ScaleTable {
    float2 v[T_STEPS];
};

constexpr double csqrt(double x) {
    double g = x > 1.0 ? x : 1.0;
    for (int i = 0; i < 60; ++i) g = 0.5 * (g + x / g);
    return g;
}

constexpr ScaleTable make_table() {
    ScaleTable tbl{};
    const double slope = (BETA_T - BETA_1) / (double)(T_STEPS - 1);
    double ab = 1.0;
    for (int i = 0; i < T_STEPS; ++i) {
        double beta = BETA_1 + slope * (double)i;
        ab *= (1.0 - beta);
        tbl.v[i].x = (float)csqrt(ab);
        tbl.v[i].y = (float)csqrt(1.0 - ab);
    }
    return tbl;
}

__constant__ ScaleTable g_scales = make_table();

// ---- mix kernel: 1 float4 per thread, 3 linear DRAM streams, streaming hints ----
// HBM-roofline-bound: 616 MB irreducible traffic @ ~6.8 TB/s achieved => ~90 us.
// total4 = B * 196 (784 floats per image = 196 float4); divides 256 exactly.

__global__ void __launch_bounds__(256) ddpm_mix_kernel(
    const float4* __restrict__ images,
    const float4* __restrict__ e,
    const int* __restrict__ t,
    float4* __restrict__ out,
    int total4)
{
    const int idx = blockIdx.x * 256 + threadIdx.x;
    if (idx >= total4) return;

    // Front-batch both 16B loads (evict-first: data is touched exactly once)
    float4 im = __ldcs(&images[idx]);
    float4 ee = __ldcs(&e[idx]);

    const unsigned b = (unsigned)idx / 196u;       // magic-mul division
    const int ti = __ldg(&t[b]);                   // alpha_bar index = t (t_s-1)
    const float2 sc = g_scales.v[ti];

    float4 o;
    o.x = fmaf(sc.x, im.x, sc.y * ee.x);
    o.y = fmaf(sc.x, im.y, sc.y * ee.y);
    o.z = fmaf(sc.x, im.z, sc.y * ee.z);
    o.w = fmaf(sc.x, im.w, sc.y * ee.w);
    __stcs(&out[idx], o);
}

extern "C" void kernel_launch(void* const* d_in, const int* in_sizes, int n_in,
                              void* d_out, int out_size) {
    const float4* images = (const float4*)d_in[0];
    const float4* e      = (const float4*)d_in[1];
    const int*    t      = (const int*)d_in[2];
    float4* out          = (float4*)d_out;

    const int B = in_sizes[2];
    const int total4 = B * 196;
    const int grid = (total4 + 255) / 256;

    ddpm_mix_kernel<<<grid, 256>>>(images, e, t, out, total4);
}

// round 9
// speedup vs baseline: 1.0249x; 1.0170x over previous
#include <cuda_runtime.h>
#include <cuda_bf16.h>

#define T_STEPS 1000
#define BETA_1 1e-4
#define BETA_T 0.02

// ---- compile-time table: (sqrt(alpha_bar[t]), sqrt(1-alpha_bar[t])) ----
// Depends only on compile-time constants; baked into __constant__ memory so
// the graph has a single kernel node and zero table-init cost at runtime.

struct ScaleTable {
    float2 v[T_STEPS];
};

constexpr double csqrt(double x) {
    double g = x > 1.0 ? x : 1.0;
    for (int i = 0; i < 60; ++i) g = 0.5 * (g + x / g);
    return g;
}

constexpr ScaleTable make_table() {
    ScaleTable tbl{};
    const double slope = (BETA_T - BETA_1) / (double)(T_STEPS - 1);
    double ab = 1.0;
    for (int i = 0; i < T_STEPS; ++i) {
        double beta = BETA_1 + slope * (double)i;
        ab *= (1.0 - beta);
        tbl.v[i].x = (float)csqrt(ab);
        tbl.v[i].y = (float)csqrt(1.0 - ab);
    }
    return tbl;
}

__constant__ ScaleTable g_scales = make_table();

// ---- mix kernel: 1 float4 per thread, 3 linear DRAM streams, streaming hints ----
// HBM-roofline-bound: 616 MB irreducible traffic @ ~6.86 TB/s achieved => ~90 us.
// total4 = B * 196 (784 floats per image = 196 float4).
// 512-thread CTAs: halves CTA count vs R6; data path identical to best config.

#define BLK 512

__global__ void __launch_bounds__(BLK) ddpm_mix_kernel(
    const float4* __restrict__ images,
    const float4* __restrict__ e,
    const int* __restrict__ t,
    float4* __restrict__ out,
    int total4)
{
    const int idx = blockIdx.x * BLK + threadIdx.x;
    if (idx >= total4) return;

    // Front-batch both 16B loads (evict-first: data is touched exactly once)
    float4 im = __ldcs(&images[idx]);
    float4 ee = __ldcs(&e[idx]);

    const unsigned b = (unsigned)idx / 196u;       // magic-mul division
    const int ti = __ldg(&t[b]);                   // alpha_bar index = t (t_s-1)
    const float2 sc = g_scales.v[ti];

    float4 o;
    o.x = fmaf(sc.x, im.x, sc.y * ee.x);
    o.y = fmaf(sc.x, im.y, sc.y * ee.y);
    o.z = fmaf(sc.x, im.z, sc.y * ee.z);
    o.w = fmaf(sc.x, im.w, sc.y * ee.w);
    __stcs(&out[idx], o);
}

extern "C" void kernel_launch(void* const* d_in, const int* in_sizes, int n_in,
                              void* d_out, int out_size) {
    const float4* images = (const float4*)d_in[0];
    const float4* e      = (const float4*)d_in[1];
    const int*    t      = (const int*)d_in[2];
    float4* out          = (float4*)d_out;

    const int B = in_sizes[2];
    const int total4 = B * 196;
    const int grid = (total4 + BLK - 1) / BLK;

    ddpm_mix_kernel<<<grid, BLK>>>(images, e, t, out, total4);
}